// round 1
// baseline (speedup 1.0000x reference)
#include <cuda_runtime.h>
#include <math_constants.h>

// Problem constants
#define N_ 4
#define T_ 2048
#define E_ 768
#define H_ 12
#define D_ 64
#define NT_ (N_*T_)    // 8192
#define NH_ (N_*H_)    // 48

// Scratch: Q,K,V in [n*H+h][t][d] layout (25.2 MB each)
__device__ float g_q[NH_*T_*D_];
__device__ float g_k[NH_*T_*D_];
__device__ float g_v[NH_*T_*D_];

// ---------------------------------------------------------------------------
// Fused QKV projection: out[m][e] = sum_k x[m][k] * W[e][k]  (y = x @ W^T)
// 64x64 block tile, BK=16, 256 threads, 4x4 microtile.
// Writes directly into [nh][t][d] scratch layout.
// ---------------------------------------------------------------------------
__global__ __launch_bounds__(256) void qkv_kernel(
    const float* __restrict__ x, const float* __restrict__ Wq,
    const float* __restrict__ Wk, const float* __restrict__ Wv) {
  __shared__ float As[16][64];   // [k][m]
  __shared__ float Bs[16][64];   // [k][e]
  const int which = blockIdx.z;
  const float* __restrict__ W = (which == 0) ? Wq : ((which == 1) ? Wk : Wv);
  float* __restrict__ out = (which == 0) ? g_q : ((which == 1) ? g_k : g_v);

  const int m0 = blockIdx.x * 64;
  const int e0 = blockIdx.y * 64;
  const int tx = threadIdx.x & 15;
  const int ty = threadIdx.x >> 4;
  const int lr = threadIdx.x >> 2;   // tile row 0..63
  const int lq = threadIdx.x & 3;    // k-quad 0..3

  float acc[4][4] = {};

  for (int k0 = 0; k0 < E_; k0 += 16) {
    float4 av = *reinterpret_cast<const float4*>(&x[(m0 + lr) * E_ + k0 + lq * 4]);
    float4 bv = *reinterpret_cast<const float4*>(&W[(e0 + lr) * E_ + k0 + lq * 4]);
    As[lq*4+0][lr] = av.x; As[lq*4+1][lr] = av.y;
    As[lq*4+2][lr] = av.z; As[lq*4+3][lr] = av.w;
    Bs[lq*4+0][lr] = bv.x; Bs[lq*4+1][lr] = bv.y;
    Bs[lq*4+2][lr] = bv.z; Bs[lq*4+3][lr] = bv.w;
    __syncthreads();
#pragma unroll
    for (int kk = 0; kk < 16; kk++) {
      float4 a = *reinterpret_cast<const float4*>(&As[kk][ty * 4]);
      float4 b = *reinterpret_cast<const float4*>(&Bs[kk][tx * 4]);
      float aa[4] = {a.x, a.y, a.z, a.w};
      float bb[4] = {b.x, b.y, b.z, b.w};
#pragma unroll
      for (int i = 0; i < 4; i++)
#pragma unroll
        for (int j = 0; j < 4; j++) acc[i][j] += aa[i] * bb[j];
    }
    __syncthreads();
  }

  // Write to [nh][t][d] layout. e0 is a multiple of 64 -> whole tile same head.
  const int h = e0 >> 6;
#pragma unroll
  for (int i = 0; i < 4; i++) {
    int m = m0 + ty * 4 + i;
    int n = m / T_;
    int t = m - n * T_;
    float4 r = make_float4(acc[i][0], acc[i][1], acc[i][2], acc[i][3]);
    *reinterpret_cast<float4*>(&out[((n * H_ + h) * T_ + t) * D_ + tx * 4]) = r;
  }
}

// ---------------------------------------------------------------------------
// Flash attention fp32: Br=Bc=64, 256 threads, online softmax.
// QsT/KsT stored transposed [d][r] for conflict-free float4 operand loads.
// P staged through shared for the PV GEMM.
// ---------------------------------------------------------------------------
__global__ __launch_bounds__(256) void attn_kernel(float* __restrict__ out) {
  extern __shared__ float sm[];
  float* QsT = sm;           // [64][64]  [d][r]
  float* KsT = sm + 4096;    // [64][64]  [d][s]
  float* Vs  = sm + 8192;    // [64][64]  [s][d]
  float* Ps  = sm + 12288;   // [64][64]  [r][s]

  const int qb = blockIdx.x;   // query block 0..31
  const int nh = blockIdx.y;   // 0..47
  const float* __restrict__ Q = g_q + (size_t)nh * T_ * D_;
  const float* __restrict__ K = g_k + (size_t)nh * T_ * D_;
  const float* __restrict__ V = g_v + (size_t)nh * T_ * D_;

  const int tx = threadIdx.x & 15;
  const int ty = threadIdx.x >> 4;
  const int lr = threadIdx.x >> 2;
  const int lq = threadIdx.x & 3;

  // Load Q tile transposed: QsT[d][r]
#pragma unroll
  for (int it = 0; it < 4; it++) {
    int c = (lq * 4 + it) * 4;   // d offset
    float4 qv = *reinterpret_cast<const float4*>(&Q[(qb * 64 + lr) * D_ + c]);
    QsT[(c + 0) * 64 + lr] = qv.x;
    QsT[(c + 1) * 64 + lr] = qv.y;
    QsT[(c + 2) * 64 + lr] = qv.z;
    QsT[(c + 3) * 64 + lr] = qv.w;
  }

  float o[4][4] = {};
  float mi[4], li[4];
#pragma unroll
  for (int i = 0; i < 4; i++) { mi[i] = -CUDART_INF_F; li[i] = 0.f; }

  for (int kb = 0; kb < T_ / 64; kb++) {
    __syncthreads();  // prev iter done with KsT/Vs/Ps; also fences Q load (iter 0)
    // Load K tile transposed + V tile natural
#pragma unroll
    for (int it = 0; it < 4; it++) {
      int c = (lq * 4 + it) * 4;
      float4 kv = *reinterpret_cast<const float4*>(&K[(kb * 64 + lr) * D_ + c]);
      KsT[(c + 0) * 64 + lr] = kv.x;
      KsT[(c + 1) * 64 + lr] = kv.y;
      KsT[(c + 2) * 64 + lr] = kv.z;
      KsT[(c + 3) * 64 + lr] = kv.w;
      float4 vv = *reinterpret_cast<const float4*>(&V[(kb * 64 + lr) * D_ + c]);
      *reinterpret_cast<float4*>(&Vs[lr * 64 + c]) = vv;
    }
    __syncthreads();

    // S = Q @ K^T
    float s[4][4] = {};
#pragma unroll 16
    for (int kk = 0; kk < 64; kk++) {
      float4 a = *reinterpret_cast<const float4*>(&QsT[kk * 64 + ty * 4]);
      float4 b = *reinterpret_cast<const float4*>(&KsT[kk * 64 + tx * 4]);
      float aa[4] = {a.x, a.y, a.z, a.w};
      float bb[4] = {b.x, b.y, b.z, b.w};
#pragma unroll
      for (int i = 0; i < 4; i++)
#pragma unroll
        for (int j = 0; j < 4; j++) s[i][j] += aa[i] * bb[j];
    }

    // Online softmax update (rows owned by 16-lane tx groups within warp)
    const float scale = 0.125f;   // 1/sqrt(64)
#pragma unroll
    for (int i = 0; i < 4; i++) {
      float mx = -CUDART_INF_F;
#pragma unroll
      for (int j = 0; j < 4; j++) { s[i][j] *= scale; mx = fmaxf(mx, s[i][j]); }
#pragma unroll
      for (int off = 1; off < 16; off <<= 1)
        mx = fmaxf(mx, __shfl_xor_sync(0xffffffffu, mx, off, 32));
      float mnew = fmaxf(mi[i], mx);
      float alpha = __expf(mi[i] - mnew);
      float rs = 0.f;
#pragma unroll
      for (int j = 0; j < 4; j++) { s[i][j] = __expf(s[i][j] - mnew); rs += s[i][j]; }
#pragma unroll
      for (int off = 1; off < 16; off <<= 1)
        rs += __shfl_xor_sync(0xffffffffu, rs, off, 32);
      li[i] = li[i] * alpha + rs;
      mi[i] = mnew;
#pragma unroll
      for (int j = 0; j < 4; j++) o[i][j] *= alpha;
    }

    // Stage P to shared (float4, conflict-free)
#pragma unroll
    for (int i = 0; i < 4; i++)
      *reinterpret_cast<float4*>(&Ps[(ty * 4 + i) * 64 + tx * 4]) =
          make_float4(s[i][0], s[i][1], s[i][2], s[i][3]);
    __syncthreads();

    // O += P @ V
#pragma unroll 16
    for (int kk = 0; kk < 64; kk++) {
      float a0 = Ps[(ty * 4 + 0) * 64 + kk];
      float a1 = Ps[(ty * 4 + 1) * 64 + kk];
      float a2 = Ps[(ty * 4 + 2) * 64 + kk];
      float a3 = Ps[(ty * 4 + 3) * 64 + kk];
      float4 b = *reinterpret_cast<const float4*>(&Vs[kk * 64 + tx * 4]);
      float bb[4] = {b.x, b.y, b.z, b.w};
#pragma unroll
      for (int j = 0; j < 4; j++) {
        o[0][j] += a0 * bb[j];
        o[1][j] += a1 * bb[j];
        o[2][j] += a2 * bb[j];
        o[3][j] += a3 * bb[j];
      }
    }
  }

  // Epilogue: normalize and write [n][t][h*64+d]
  const int n = nh / H_;
  const int h = nh - n * H_;
#pragma unroll
  for (int i = 0; i < 4; i++) {
    float inv = 1.f / li[i];
    int t = qb * 64 + ty * 4 + i;
    float4 r = make_float4(o[i][0] * inv, o[i][1] * inv, o[i][2] * inv, o[i][3] * inv);
    *reinterpret_cast<float4*>(&out[((size_t)n * T_ + t) * E_ + h * D_ + tx * 4]) = r;
  }
}

extern "C" void kernel_launch(void* const* d_in, const int* in_sizes, int n_in,
                              void* d_out, int out_size) {
  const float* x  = (const float*)d_in[0];
  const float* Wq = (const float*)d_in[1];
  const float* Wk = (const float*)d_in[2];
  const float* Wv = (const float*)d_in[3];
  float* out = (float*)d_out;

  dim3 gq(NT_ / 64, E_ / 64, 3);
  qkv_kernel<<<gq, 256>>>(x, Wq, Wk, Wv);

  cudaFuncSetAttribute(attn_kernel, cudaFuncAttributeMaxDynamicSharedMemorySize, 65536);
  dim3 ga(T_ / 64, NH_);
  attn_kernel<<<ga, 256, 65536>>>(out);
}

// round 2
// speedup vs baseline: 1.4587x; 1.4587x over previous
#include <cuda_runtime.h>
#include <math_constants.h>
#include <cstdint>

// Problem constants
#define N_ 4
#define T_ 2048
#define E_ 768
#define H_ 12
#define D_ 64
#define NT_ (N_*T_)    // 8192
#define NH_ (N_*H_)    // 48

// Scratch: Q,K,V in [n*H+h][t][d] layout
__device__ float g_q[NH_*T_*D_];
__device__ float g_k[NH_*T_*D_];
__device__ float g_v[NH_*T_*D_];

__device__ __forceinline__ uint32_t f2tf(float f) {
  uint32_t u;
  asm("cvt.rna.tf32.f32 %0, %1;" : "=r"(u) : "f"(f));
  return u;
}

// D = A*B + D, m16n8k8 tf32
__device__ __forceinline__ void mma8(float* c, uint32_t a0, uint32_t a1,
                                     uint32_t a2, uint32_t a3,
                                     uint32_t b0, uint32_t b1) {
  asm volatile(
      "mma.sync.aligned.m16n8k8.row.col.f32.tf32.tf32.f32 "
      "{%0,%1,%2,%3},{%4,%5,%6,%7},{%8,%9},{%0,%1,%2,%3};"
      : "+f"(c[0]), "+f"(c[1]), "+f"(c[2]), "+f"(c[3])
      : "r"(a0), "r"(a1), "r"(a2), "r"(a3), "r"(b0), "r"(b1));
}

// ---------------------------------------------------------------------------
// QKV projection (tf32 mma): out[m][e] = sum_k x[m][k]*W[e][k]
// CTA tile 128(m) x 64(e), BK=32, 256 threads = 8 warps (4m x 2n), warp 32x32.
// Smem k-permuted within groups of 8: k' = 2*(k&3) + ((k>>2)&1)
// so each fragment pair is one LDS.64.
// ---------------------------------------------------------------------------
#define LDK 34   // padded row stride (32 k' cols + 2 pad)

__global__ __launch_bounds__(256) void qkv_kernel(
    const float* __restrict__ x, const float* __restrict__ Wq,
    const float* __restrict__ Wk, const float* __restrict__ Wv) {
  __shared__ uint32_t As[128 * LDK];
  __shared__ uint32_t Bs[64 * LDK];

  const int which = blockIdx.z;
  const float* __restrict__ W = (which == 0) ? Wq : ((which == 1) ? Wk : Wv);
  float* __restrict__ out = (which == 0) ? g_q : ((which == 1) ? g_k : g_v);

  const int m0 = blockIdx.x * 128;
  const int h  = blockIdx.y;          // 64-wide E tile == one head
  const int tid = threadIdx.x;
  const int lane = tid & 31;
  const int wid = tid >> 5;
  const int wm = wid & 3;             // 0..3
  const int wn = wid >> 2;            // 0..1
  const int g = lane >> 2;            // group id 0..7
  const int t4 = lane & 3;            // thread-in-group 0..3

  // load assignment: 8 float4-columns across BK=32, row = tid>>3
  const int lr = tid >> 3;            // 0..31
  const int c4 = (tid & 7) * 4;       // 0,4,...,28
  const int pg = c4 >> 3;             // k-group within chunk
  const int pq = (c4 >> 2) & 1;       // low/high half of group

  float acc[2][4][4] = {};

  for (int k0 = 0; k0 < E_; k0 += 32) {
    __syncthreads();
    // A tile: 128 rows
#pragma unroll
    for (int p = 0; p < 4; p++) {
      int row = lr + p * 32;
      float4 v = *reinterpret_cast<const float4*>(&x[(m0 + row) * E_ + k0 + c4]);
      uint32_t* dst = &As[row * LDK + pg * 8 + pq];
      dst[0] = f2tf(v.x); dst[2] = f2tf(v.y);
      dst[4] = f2tf(v.z); dst[6] = f2tf(v.w);
    }
    // B tile: 64 rows
#pragma unroll
    for (int p = 0; p < 2; p++) {
      int row = lr + p * 32;
      float4 v = *reinterpret_cast<const float4*>(&W[(h * 64 + row) * E_ + k0 + c4]);
      uint32_t* dst = &Bs[row * LDK + pg * 8 + pq];
      dst[0] = f2tf(v.x); dst[2] = f2tf(v.y);
      dst[4] = f2tf(v.z); dst[6] = f2tf(v.w);
    }
    __syncthreads();

#pragma unroll
    for (int ks = 0; ks < 4; ks++) {
      const int koff = ks * 8 + 2 * t4;
      uint32_t a[2][4];
#pragma unroll
      for (int i = 0; i < 2; i++) {
        int row = wm * 32 + i * 16 + g;
        uint2 lo = *reinterpret_cast<const uint2*>(&As[row * LDK + koff]);
        uint2 hi = *reinterpret_cast<const uint2*>(&As[(row + 8) * LDK + koff]);
        a[i][0] = lo.x; a[i][1] = hi.x; a[i][2] = lo.y; a[i][3] = hi.y;
      }
#pragma unroll
      for (int j = 0; j < 4; j++) {
        int n = wn * 32 + j * 8 + g;
        uint2 b = *reinterpret_cast<const uint2*>(&Bs[n * LDK + koff]);
#pragma unroll
        for (int i = 0; i < 2; i++)
          mma8(acc[i][j], a[i][0], a[i][1], a[i][2], a[i][3], b.x, b.y);
      }
    }
  }

  // Epilogue: write into [nh][t][d] layout
#pragma unroll
  for (int i = 0; i < 2; i++) {
#pragma unroll
    for (int j = 0; j < 4; j++) {
      int d = wn * 32 + j * 8 + 2 * t4;
      int m = m0 + wm * 32 + i * 16 + g;
      {
        int n = m >> 11, tt = m & (T_ - 1);
        float2 r = make_float2(acc[i][j][0], acc[i][j][1]);
        *reinterpret_cast<float2*>(
            &out[((size_t)(n * H_ + h) * T_ + tt) * D_ + d]) = r;
      }
      {
        int m2 = m + 8;
        int n = m2 >> 11, tt = m2 & (T_ - 1);
        float2 r = make_float2(acc[i][j][2], acc[i][j][3]);
        *reinterpret_cast<float2*>(
            &out[((size_t)(n * H_ + h) * T_ + tt) * D_ + d]) = r;
      }
    }
  }
}

// ---------------------------------------------------------------------------
// Flash attention with tf32 mma. Br=Bc=64, D=64, 128 threads = 4 warps,
// each warp owns 16 query rows. K-permuted smem layouts for 1-LDS.64 frags.
// ---------------------------------------------------------------------------
#define LDS_ 66   // padded row stride for 64 cols

__global__ __launch_bounds__(128) void attn_kernel(float* __restrict__ out) {
  extern __shared__ uint32_t sm[];
  uint32_t* Qs = sm;                 // [64][66] rows r, perm-d
  uint32_t* Ks = sm + 64 * LDS_;     // [64][66] rows s, perm-d
  uint32_t* Vs = sm + 2 * 64 * LDS_; // [64][66] rows d, perm-s (transposed)
  uint32_t* Ps = sm + 3 * 64 * LDS_; // [64][66] rows r, perm-s

  const int qb = blockIdx.x;
  const int nh = blockIdx.y;
  const float* __restrict__ Q = g_q + (size_t)nh * T_ * D_;
  const float* __restrict__ K = g_k + (size_t)nh * T_ * D_;
  const float* __restrict__ V = g_v + (size_t)nh * T_ * D_;

  const int tid = threadIdx.x;
  const int lane = tid & 31;
  const int wid = tid >> 5;
  const int g = lane >> 2;
  const int t4 = lane & 3;

  // loader mapping: 16 float4-cols x 8 rows (x8 passes)
  const int lr = tid >> 4;            // 0..7
  const int c4 = (tid & 15) * 4;      // 0..60
  const int pg = c4 >> 3;
  const int pq = (c4 >> 2) & 1;

  // Load Q tile once (rows qb*64 .. +63), perm-d layout
#pragma unroll
  for (int p = 0; p < 8; p++) {
    int row = lr + p * 8;
    float4 v = *reinterpret_cast<const float4*>(&Q[(qb * 64 + row) * D_ + c4]);
    uint32_t* dst = &Qs[row * LDS_ + pg * 8 + pq];
    dst[0] = f2tf(v.x); dst[2] = f2tf(v.y);
    dst[4] = f2tf(v.z); dst[6] = f2tf(v.w);
  }

  float o[8][4] = {};
  float mi[2] = {-CUDART_INF_F, -CUDART_INF_F};
  float li[2] = {0.f, 0.f};

  for (int kb = 0; kb < T_ / 64; kb++) {
    __syncthreads();  // Ks/Vs free from previous iteration (and Qs on iter 0)
#pragma unroll
    for (int p = 0; p < 8; p++) {
      int row = lr + p * 8;
      // K: rows s, perm-d (B operand of S = Q K^T)
      float4 kv = *reinterpret_cast<const float4*>(&K[(kb * 64 + row) * D_ + c4]);
      uint32_t* dst = &Ks[row * LDS_ + pg * 8 + pq];
      dst[0] = f2tf(kv.x); dst[2] = f2tf(kv.y);
      dst[4] = f2tf(kv.z); dst[6] = f2tf(kv.w);
      // V: transpose into rows d, perm-s (B operand of O += P V)
      float4 vv = *reinterpret_cast<const float4*>(&V[(kb * 64 + row) * D_ + c4]);
      int scol = (row >> 3) * 8 + 2 * (row & 3) + ((row >> 2) & 1);
      Vs[(c4 + 0) * LDS_ + scol] = f2tf(vv.x);
      Vs[(c4 + 1) * LDS_ + scol] = f2tf(vv.y);
      Vs[(c4 + 2) * LDS_ + scol] = f2tf(vv.z);
      Vs[(c4 + 3) * LDS_ + scol] = f2tf(vv.w);
    }
    __syncthreads();

    // ---- S = Q @ K^T (warp: 16 rows x 64 cols) ----
    float sacc[8][4] = {};
#pragma unroll
    for (int ks = 0; ks < 8; ks++) {
      const int koff = ks * 8 + 2 * t4;
      int rA = wid * 16 + g;
      uint2 lo = *reinterpret_cast<const uint2*>(&Qs[rA * LDS_ + koff]);
      uint2 hi = *reinterpret_cast<const uint2*>(&Qs[(rA + 8) * LDS_ + koff]);
#pragma unroll
      for (int j = 0; j < 8; j++) {
        int n = j * 8 + g;
        uint2 b = *reinterpret_cast<const uint2*>(&Ks[n * LDS_ + koff]);
        mma8(sacc[j], lo.x, hi.x, lo.y, hi.y, b.x, b.y);
      }
    }

    // ---- online softmax (per thread: 2 rows) ----
    const float scale = 0.125f;  // 1/sqrt(64)
#pragma unroll
    for (int rh = 0; rh < 2; rh++) {
      float mx = -CUDART_INF_F;
#pragma unroll
      for (int j = 0; j < 8; j++) {
        sacc[j][2 * rh]     *= scale;
        sacc[j][2 * rh + 1] *= scale;
        mx = fmaxf(mx, fmaxf(sacc[j][2 * rh], sacc[j][2 * rh + 1]));
      }
      mx = fmaxf(mx, __shfl_xor_sync(0xffffffffu, mx, 1));
      mx = fmaxf(mx, __shfl_xor_sync(0xffffffffu, mx, 2));
      float mnew = fmaxf(mi[rh], mx);
      float alpha = __expf(mi[rh] - mnew);
      float rs = 0.f;
#pragma unroll
      for (int j = 0; j < 8; j++) {
        sacc[j][2 * rh]     = __expf(sacc[j][2 * rh] - mnew);
        sacc[j][2 * rh + 1] = __expf(sacc[j][2 * rh + 1] - mnew);
        rs += sacc[j][2 * rh] + sacc[j][2 * rh + 1];
      }
      rs += __shfl_xor_sync(0xffffffffu, rs, 1);
      rs += __shfl_xor_sync(0xffffffffu, rs, 2);
      li[rh] = li[rh] * alpha + rs;
      mi[rh] = mnew;
#pragma unroll
      for (int j = 0; j < 8; j++) {
        o[j][2 * rh]     *= alpha;
        o[j][2 * rh + 1] *= alpha;
      }
    }

    // ---- stage P to warp-private smem rows (perm-s layout) ----
    {
      int k0 = 2 * t4, k1 = 2 * t4 + 1;
      int pos0 = 2 * (k0 & 3) + ((k0 >> 2) & 1);
      int pos1 = 2 * (k1 & 3) + ((k1 >> 2) & 1);
#pragma unroll
      for (int j = 0; j < 8; j++) {
#pragma unroll
        for (int rh = 0; rh < 2; rh++) {
          int row = wid * 16 + g + rh * 8;
          Ps[row * LDS_ + j * 8 + pos0] = f2tf(sacc[j][2 * rh]);
          Ps[row * LDS_ + j * 8 + pos1] = f2tf(sacc[j][2 * rh + 1]);
        }
      }
    }
    __syncwarp();

    // ---- O += P @ V ----
#pragma unroll
    for (int ks = 0; ks < 8; ks++) {
      const int koff = ks * 8 + 2 * t4;
      int rA = wid * 16 + g;
      uint2 lo = *reinterpret_cast<const uint2*>(&Ps[rA * LDS_ + koff]);
      uint2 hi = *reinterpret_cast<const uint2*>(&Ps[(rA + 8) * LDS_ + koff]);
#pragma unroll
      for (int j = 0; j < 8; j++) {
        int d = j * 8 + g;
        uint2 b = *reinterpret_cast<const uint2*>(&Vs[d * LDS_ + koff]);
        mma8(o[j], lo.x, hi.x, lo.y, hi.y, b.x, b.y);
      }
    }
    __syncwarp();  // Ps reads done before next iteration's writes
  }

  // ---- epilogue ----
  const int n = nh / H_;
  const int h = nh - n * H_;
#pragma unroll
  for (int rh = 0; rh < 2; rh++) {
    float inv = 1.f / li[rh];
    int tt = qb * 64 + wid * 16 + g + rh * 8;
#pragma unroll
    for (int j = 0; j < 8; j++) {
      int d = j * 8 + 2 * t4;
      float2 r = make_float2(o[j][2 * rh] * inv, o[j][2 * rh + 1] * inv);
      *reinterpret_cast<float2*>(
          &out[((size_t)n * T_ + tt) * E_ + h * D_ + d]) = r;
    }
  }
}

extern "C" void kernel_launch(void* const* d_in, const int* in_sizes, int n_in,
                              void* d_out, int out_size) {
  const float* x  = (const float*)d_in[0];
  const float* Wq = (const float*)d_in[1];
  const float* Wk = (const float*)d_in[2];
  const float* Wv = (const float*)d_in[3];
  float* out = (float*)d_out;

  dim3 gq(NT_ / 128, E_ / 64, 3);
  qkv_kernel<<<gq, 256>>>(x, Wq, Wk, Wv);

  const int attn_smem = 4 * 64 * LDS_ * 4;  // 67584 bytes
  cudaFuncSetAttribute(attn_kernel, cudaFuncAttributeMaxDynamicSharedMemorySize,
                       attn_smem);
  dim3 ga(T_ / 64, NH_);
  attn_kernel<<<ga, 128, attn_smem>>>(out);
}

// round 4
// speedup vs baseline: 1.8156x; 1.2447x over previous
#include <cuda_runtime.h>
#include <math_constants.h>
#include <cstdint>

// Problem constants
#define N_ 4
#define T_ 2048
#define E_ 768
#define H_ 12
#define D_ 64
#define NT_ (N_*T_)    // 8192
#define NH_ (N_*H_)    // 48

// Scratch: Q,K,V in [n*H+h][t][d] layout
__device__ float g_q[NH_*T_*D_];
__device__ float g_k[NH_*T_*D_];
__device__ float g_v[NH_*T_*D_];

__device__ __forceinline__ uint32_t f2tf(float f) {
  uint32_t u;
  asm("cvt.rna.tf32.f32 %0, %1;" : "=r"(u) : "f"(f));
  return u;
}

// D = A*B + D, m16n8k8 tf32
__device__ __forceinline__ void mma8(float* c, uint32_t a0, uint32_t a1,
                                     uint32_t a2, uint32_t a3,
                                     uint32_t b0, uint32_t b1) {
  asm volatile(
      "mma.sync.aligned.m16n8k8.row.col.f32.tf32.tf32.f32 "
      "{%0,%1,%2,%3},{%4,%5,%6,%7},{%8,%9},{%0,%1,%2,%3};"
      : "+f"(c[0]), "+f"(c[1]), "+f"(c[2]), "+f"(c[3])
      : "r"(a0), "r"(a1), "r"(a2), "r"(a3), "r"(b0), "r"(b1));
}

// Write one float4 (k-cols of a row) into perm layout:
// pos(k) = 2*(k&3) + ((k>>2)&1) within each 8-group, so mma fragment pairs
// (k, k+4) are adjacent -> one LDS.64. Lane-pair exchange (lane^1) turns the
// scattered stores into 2x STS.64. dst8 = &row_base[pg*8].
__device__ __forceinline__ void store_perm(uint32_t* dst8, float4 v, int pq) {
  float s1 = pq ? v.x : v.z;
  float s2 = pq ? v.y : v.w;
  float r1 = __shfl_xor_sync(0xffffffffu, s1, 1);
  float r2 = __shfl_xor_sync(0xffffffffu, s2, 1);
  uint2 w0, w1;
  if (pq == 0) {
    w0 = make_uint2(f2tf(v.x), f2tf(r1));   // cols 0,1 = k0,k4
    w1 = make_uint2(f2tf(v.y), f2tf(r2));   // cols 2,3 = k1,k5
  } else {
    w0 = make_uint2(f2tf(r1), f2tf(v.z));   // cols 4,5 = k2,k6
    w1 = make_uint2(f2tf(r2), f2tf(v.w));   // cols 6,7 = k3,k7
  }
  *reinterpret_cast<uint2*>(dst8 + 4 * pq) = w0;
  *reinterpret_cast<uint2*>(dst8 + 4 * pq + 2) = w1;
}

// ---------------------------------------------------------------------------
// QKV projection (tf32 mma): out[m][e] = sum_k x[m][k]*W[e][k]
// CTA 128(m) x 128(e), BK=32, 256 threads = 8 warps (wm 4 x wn 2),
// warp tile 32(m) x 64(e). Rows are 32 words wide -> stride 40 valid here.
// ---------------------------------------------------------------------------
#define QST 40

__global__ __launch_bounds__(256, 2) void qkv_kernel(
    const float* __restrict__ x, const float* __restrict__ Wq,
    const float* __restrict__ Wk, const float* __restrict__ Wv) {
  __shared__ uint32_t As[128 * QST];
  __shared__ uint32_t Bs[128 * QST];

  const int which = blockIdx.z;
  const float* __restrict__ W = (which == 0) ? Wq : ((which == 1) ? Wk : Wv);
  float* __restrict__ out = (which == 0) ? g_q : ((which == 1) ? g_k : g_v);

  const int m0 = blockIdx.x * 128;
  const int e0 = blockIdx.y * 128;
  const int tid = threadIdx.x;
  const int lane = tid & 31;
  const int wid = tid >> 5;
  const int wm = wid & 3;
  const int wn = wid >> 2;
  const int g = lane >> 2;
  const int t4 = lane & 3;

  // loader mapping: row = tid>>3 (0..31), float4 col = tid&7 (0..7, 32 k-cols)
  const int lr = tid >> 3;
  const int cq = tid & 7;
  const int pg = cq >> 1;           // 8-group 0..3
  const int pq = tid & 1;

  float acc[2][8][4] = {};

  for (int k0 = 0; k0 < E_; k0 += 32) {
    __syncthreads();
#pragma unroll
    for (int p = 0; p < 4; p++) {
      int row = lr + p * 32;
      float4 av = *reinterpret_cast<const float4*>(&x[(m0 + row) * E_ + k0 + cq * 4]);
      store_perm(&As[row * QST + pg * 8], av, pq);
      float4 bv = *reinterpret_cast<const float4*>(&W[(e0 + row) * E_ + k0 + cq * 4]);
      store_perm(&Bs[row * QST + pg * 8], bv, pq);
    }
    __syncthreads();

#pragma unroll
    for (int ks = 0; ks < 4; ks++) {
      const int koff = ks * 8 + 2 * t4;
      uint2 alo[2], ahi[2];
#pragma unroll
      for (int i = 0; i < 2; i++) {
        int row = wm * 32 + i * 16 + g;
        alo[i] = *reinterpret_cast<const uint2*>(&As[row * QST + koff]);
        ahi[i] = *reinterpret_cast<const uint2*>(&As[(row + 8) * QST + koff]);
      }
#pragma unroll
      for (int j = 0; j < 8; j++) {
        int n = wn * 64 + j * 8 + g;
        uint2 b = *reinterpret_cast<const uint2*>(&Bs[n * QST + koff]);
#pragma unroll
        for (int i = 0; i < 2; i++)
          mma8(acc[i][j], alo[i].x, ahi[i].x, alo[i].y, ahi[i].y, b.x, b.y);
      }
    }
  }

  // Epilogue into [nh][t][d]
  const int h = (e0 >> 6) + wn;     // head constant per warp
#pragma unroll
  for (int i = 0; i < 2; i++) {
#pragma unroll
    for (int j = 0; j < 8; j++) {
      int d = j * 8 + 2 * t4;
      int m = m0 + wm * 32 + i * 16 + g;
      {
        int n = m >> 11, tt = m & (T_ - 1);
        *reinterpret_cast<float2*>(
            &out[((size_t)(n * H_ + h) * T_ + tt) * D_ + d]) =
            make_float2(acc[i][j][0], acc[i][j][1]);
      }
      {
        int m2 = m + 8;
        int n = m2 >> 11, tt = m2 & (T_ - 1);
        *reinterpret_cast<float2*>(
            &out[((size_t)(n * H_ + h) * T_ + tt) * D_ + d]) =
            make_float2(acc[i][j][2], acc[i][j][3]);
      }
    }
  }
}

// ---------------------------------------------------------------------------
// Flash attention, tf32 mma. Br=128, Bc=64, 128 threads = 4 warps,
// warp owns 32 query rows (2 M-tiles). Rows are 64 words wide ->
// stride 72 (72 mod 32 == 8, same conflict-free residue as 40).
// Q/K/V: rows x perm-d.  P: rows x perm-s with xor-2 swizzle on (g>>2).
// ---------------------------------------------------------------------------
#define AST 72

__global__ __launch_bounds__(128, 2) void attn_kernel(float* __restrict__ out) {
  extern __shared__ uint32_t sm[];
  uint32_t* Qs = sm;                   // [128][AST]
  uint32_t* Ks = Qs + 128 * AST;       // [64][AST]
  uint32_t* Vs = Ks + 64 * AST;        // [64][AST]
  uint32_t* Ps = Vs + 64 * AST;        // [128][AST]

  const int qb = blockIdx.x;
  const int nh = blockIdx.y;
  const float* __restrict__ Q = g_q + (size_t)nh * T_ * D_;
  const float* __restrict__ K = g_k + (size_t)nh * T_ * D_;
  const float* __restrict__ V = g_v + (size_t)nh * T_ * D_;

  const int tid = threadIdx.x;
  const int lane = tid & 31;
  const int wid = tid >> 5;
  const int g = lane >> 2;
  const int t4 = lane & 3;
  const int wbase = wid * 32;
  const int sw = (g & 4) >> 1;                     // xor swizzle for Ps
  const int posg = 2 * (g & 3) + ((g >> 2) & 1);   // perm pos of d=g

  // loader mapping: row = tid>>4 (0..7), float4 col = tid&15 (64 d-cols)
  const int lr = tid >> 4;
  const int cq = tid & 15;
  const int pg = cq >> 1;         // 8-group 0..7
  const int pq = tid & 1;

  // Load Q tile (128 rows)
#pragma unroll
  for (int p = 0; p < 16; p++) {
    int row = lr + p * 8;
    float4 qv = *reinterpret_cast<const float4*>(&Q[(qb * 128 + row) * D_ + cq * 4]);
    store_perm(&Qs[row * AST + pg * 8], qv, pq);
  }

  float o[2][8][4] = {};
  float mi[4], li[4];
#pragma unroll
  for (int s = 0; s < 4; s++) { mi[s] = -CUDART_INF_F; li[s] = 0.f; }

  for (int kb = 0; kb < T_ / 64; kb++) {
    __syncthreads();  // Ks/Vs free (and Qs visible on iter 0)
#pragma unroll
    for (int p = 0; p < 8; p++) {
      int row = lr + p * 8;
      float4 kv = *reinterpret_cast<const float4*>(&K[(kb * 64 + row) * D_ + cq * 4]);
      store_perm(&Ks[row * AST + pg * 8], kv, pq);
      float4 vv = *reinterpret_cast<const float4*>(&V[(kb * 64 + row) * D_ + cq * 4]);
      store_perm(&Vs[row * AST + pg * 8], vv, pq);
    }
    __syncthreads();

    // ---- S = Q @ K^T : warp computes 32 x 64 ----
    float sacc[2][8][4] = {};
#pragma unroll
    for (int ks = 0; ks < 8; ks++) {
      const int koff = ks * 8 + 2 * t4;
      uint2 alo[2], ahi[2];
#pragma unroll
      for (int i = 0; i < 2; i++) {
        int row = wbase + i * 16 + g;
        alo[i] = *reinterpret_cast<const uint2*>(&Qs[row * AST + koff]);
        ahi[i] = *reinterpret_cast<const uint2*>(&Qs[(row + 8) * AST + koff]);
      }
#pragma unroll
      for (int j = 0; j < 8; j++) {
        int n = j * 8 + g;
        uint2 b = *reinterpret_cast<const uint2*>(&Ks[n * AST + koff]);
#pragma unroll
        for (int i = 0; i < 2; i++)
          mma8(sacc[i][j], alo[i].x, ahi[i].x, alo[i].y, ahi[i].y, b.x, b.y);
      }
    }

    // ---- online softmax: 4 row-slots per thread ----
    const float scale = 0.125f;
#pragma unroll
    for (int i = 0; i < 2; i++) {
#pragma unroll
      for (int rh = 0; rh < 2; rh++) {
        const int s = i * 2 + rh;
        float mx = -CUDART_INF_F;
#pragma unroll
        for (int j = 0; j < 8; j++) {
          sacc[i][j][2 * rh]     *= scale;
          sacc[i][j][2 * rh + 1] *= scale;
          mx = fmaxf(mx, fmaxf(sacc[i][j][2 * rh], sacc[i][j][2 * rh + 1]));
        }
        mx = fmaxf(mx, __shfl_xor_sync(0xffffffffu, mx, 1));
        mx = fmaxf(mx, __shfl_xor_sync(0xffffffffu, mx, 2));
        float mnew = fmaxf(mi[s], mx);
        float alpha = __expf(mi[s] - mnew);
        float rs = 0.f;
#pragma unroll
        for (int j = 0; j < 8; j++) {
          sacc[i][j][2 * rh]     = __expf(sacc[i][j][2 * rh] - mnew);
          sacc[i][j][2 * rh + 1] = __expf(sacc[i][j][2 * rh + 1] - mnew);
          rs += sacc[i][j][2 * rh] + sacc[i][j][2 * rh + 1];
        }
        rs += __shfl_xor_sync(0xffffffffu, rs, 1);
        rs += __shfl_xor_sync(0xffffffffu, rs, 2);
        li[s] = li[s] * alpha + rs;
        mi[s] = mnew;
#pragma unroll
        for (int j = 0; j < 8; j++) {
          o[i][j][2 * rh]     *= alpha;
          o[i][j][2 * rh + 1] *= alpha;
        }
      }
    }

    // ---- stage P (perm-s + xor swizzle), warp-private rows ----
    {
      const int k0 = 2 * t4;
      const int pos0 = (2 * (k0 & 3) + ((k0 >> 2) & 1)) ^ sw;
      const int pos1 = (2 * ((k0 + 1) & 3) + (((k0 + 1) >> 2) & 1)) ^ sw;
#pragma unroll
      for (int i = 0; i < 2; i++) {
        int row = wbase + i * 16 + g;
#pragma unroll
        for (int j = 0; j < 8; j++) {
          Ps[row * AST + j * 8 + pos0]       = f2tf(sacc[i][j][0]);
          Ps[row * AST + j * 8 + pos1]       = f2tf(sacc[i][j][1]);
          Ps[(row + 8) * AST + j * 8 + pos0] = f2tf(sacc[i][j][2]);
          Ps[(row + 8) * AST + j * 8 + pos1] = f2tf(sacc[i][j][3]);
        }
      }
    }
    __syncwarp();

    // ---- O += P @ V ----
#pragma unroll
    for (int ks = 0; ks < 8; ks++) {
      const int koffA = ks * 8 + ((2 * t4) ^ sw);
      uint2 alo[2], ahi[2];
#pragma unroll
      for (int i = 0; i < 2; i++) {
        int row = wbase + i * 16 + g;
        alo[i] = *reinterpret_cast<const uint2*>(&Ps[row * AST + koffA]);
        ahi[i] = *reinterpret_cast<const uint2*>(&Ps[(row + 8) * AST + koffA]);
      }
#pragma unroll
      for (int j = 0; j < 8; j++) {
        uint32_t b0 = Vs[(ks * 8 + t4) * AST + j * 8 + posg];
        uint32_t b1 = Vs[(ks * 8 + t4 + 4) * AST + j * 8 + posg];
#pragma unroll
        for (int i = 0; i < 2; i++)
          mma8(o[i][j], alo[i].x, ahi[i].x, alo[i].y, ahi[i].y, b0, b1);
      }
    }
    __syncwarp();  // Ps reads done before next iteration's writes
  }

  // ---- epilogue ----
  const int n = nh / H_;
  const int h = nh - n * H_;
#pragma unroll
  for (int i = 0; i < 2; i++) {
#pragma unroll
    for (int rh = 0; rh < 2; rh++) {
      float inv = 1.f / li[i * 2 + rh];
      int t = qb * 128 + wbase + i * 16 + rh * 8 + g;
#pragma unroll
      for (int j = 0; j < 8; j++) {
        int d = j * 8 + 2 * t4;
        *reinterpret_cast<float2*>(
            &out[((size_t)n * T_ + t) * E_ + h * D_ + d]) =
            make_float2(o[i][j][2 * rh] * inv, o[i][j][2 * rh + 1] * inv);
      }
    }
  }
}

extern "C" void kernel_launch(void* const* d_in, const int* in_sizes, int n_in,
                              void* d_out, int out_size) {
  const float* x  = (const float*)d_in[0];
  const float* Wq = (const float*)d_in[1];
  const float* Wk = (const float*)d_in[2];
  const float* Wv = (const float*)d_in[3];
  float* out = (float*)d_out;

  dim3 gq(NT_ / 128, E_ / 128, 3);
  qkv_kernel<<<gq, 256>>>(x, Wq, Wk, Wv);

  const int attn_smem = (128 + 64 + 64 + 128) * AST * 4;  // 110592 B
  cudaFuncSetAttribute(attn_kernel, cudaFuncAttributeMaxDynamicSharedMemorySize,
                       attn_smem);
  dim3 ga(T_ / 128, NH_);
  attn_kernel<<<ga, 128, attn_smem>>>(out);
}

// round 5
// speedup vs baseline: 2.7952x; 1.5395x over previous
#include <cuda_runtime.h>
#include <math_constants.h>
#include <cstdint>

// Problem constants
#define N_ 4
#define T_ 2048
#define E_ 768
#define H_ 12
#define D_ 64
#define NT_ (N_*T_)    // 8192
#define NH_ (N_*H_)    // 48

// Scratch: Q,K,V in [n*H+h][t][d] layout, values pre-rounded to tf32
__device__ float g_q[NH_*T_*D_];
__device__ float g_k[NH_*T_*D_];
__device__ float g_v[NH_*T_*D_];

__device__ __forceinline__ uint32_t f2tf(float f) {
  uint32_t u;
  asm("cvt.rna.tf32.f32 %0, %1;" : "=r"(u) : "f"(f));
  return u;
}

// D = A*B + D, m16n8k8 tf32
__device__ __forceinline__ void mma8(float* c, uint32_t a0, uint32_t a1,
                                     uint32_t a2, uint32_t a3,
                                     uint32_t b0, uint32_t b1) {
  asm volatile(
      "mma.sync.aligned.m16n8k8.row.col.f32.tf32.tf32.f32 "
      "{%0,%1,%2,%3},{%4,%5,%6,%7},{%8,%9},{%0,%1,%2,%3};"
      : "+f"(c[0]), "+f"(c[1]), "+f"(c[2]), "+f"(c[3])
      : "r"(a0), "r"(a1), "r"(a2), "r"(a3), "r"(b0), "r"(b1));
}

__device__ __forceinline__ void cp16(uint32_t smem_addr, const void* gptr) {
  asm volatile("cp.async.cg.shared.global [%0], [%1], 16;"
               :: "r"(smem_addr), "l"(gptr));
}
__device__ __forceinline__ void cp_commit() {
  asm volatile("cp.async.commit_group;");
}
__device__ __forceinline__ void cp_wait0() {
  asm volatile("cp.async.wait_group 0;");
}

// Write one float4 (k-cols of a row) into perm layout (QKV kernel only):
// pos(k) = 2*(k&3) + ((k>>2)&1) within each 8-group, so mma fragment pairs
// (k, k+4) are adjacent -> one LDS.64. Lane-pair exchange (lane^1) turns the
// scattered stores into 2x STS.64. dst8 = &row_base[pg*8].
__device__ __forceinline__ void store_perm(uint32_t* dst8, float4 v, int pq) {
  float s1 = pq ? v.x : v.z;
  float s2 = pq ? v.y : v.w;
  float r1 = __shfl_xor_sync(0xffffffffu, s1, 1);
  float r2 = __shfl_xor_sync(0xffffffffu, s2, 1);
  uint2 w0, w1;
  if (pq == 0) {
    w0 = make_uint2(f2tf(v.x), f2tf(r1));   // cols 0,1 = k0,k4
    w1 = make_uint2(f2tf(v.y), f2tf(r2));   // cols 2,3 = k1,k5
  } else {
    w0 = make_uint2(f2tf(r1), f2tf(v.z));   // cols 4,5 = k2,k6
    w1 = make_uint2(f2tf(r2), f2tf(v.w));   // cols 6,7 = k3,k7
  }
  *reinterpret_cast<uint2*>(dst8 + 4 * pq) = w0;
  *reinterpret_cast<uint2*>(dst8 + 4 * pq + 2) = w1;
}

// ---------------------------------------------------------------------------
// QKV projection (tf32 mma): out[m][e] = sum_k x[m][k]*W[e][k]
// CTA 128(m) x 128(e), BK=32, 256 threads = 8 warps (wm 4 x wn 2),
// warp tile 32(m) x 64(e). Epilogue stores tf32-rounded values.
// ---------------------------------------------------------------------------
#define QST 40

__global__ __launch_bounds__(256, 2) void qkv_kernel(
    const float* __restrict__ x, const float* __restrict__ Wq,
    const float* __restrict__ Wk, const float* __restrict__ Wv) {
  __shared__ uint32_t As[128 * QST];
  __shared__ uint32_t Bs[128 * QST];

  const int which = blockIdx.z;
  const float* __restrict__ W = (which == 0) ? Wq : ((which == 1) ? Wk : Wv);
  float* __restrict__ out = (which == 0) ? g_q : ((which == 1) ? g_k : g_v);

  const int m0 = blockIdx.x * 128;
  const int e0 = blockIdx.y * 128;
  const int tid = threadIdx.x;
  const int lane = tid & 31;
  const int wid = tid >> 5;
  const int wm = wid & 3;
  const int wn = wid >> 2;
  const int g = lane >> 2;
  const int t4 = lane & 3;

  const int lr = tid >> 3;
  const int cq = tid & 7;
  const int pg = cq >> 1;
  const int pq = tid & 1;

  float acc[2][8][4] = {};

  for (int k0 = 0; k0 < E_; k0 += 32) {
    __syncthreads();
#pragma unroll
    for (int p = 0; p < 4; p++) {
      int row = lr + p * 32;
      float4 av = *reinterpret_cast<const float4*>(&x[(m0 + row) * E_ + k0 + cq * 4]);
      store_perm(&As[row * QST + pg * 8], av, pq);
      float4 bv = *reinterpret_cast<const float4*>(&W[(e0 + row) * E_ + k0 + cq * 4]);
      store_perm(&Bs[row * QST + pg * 8], bv, pq);
    }
    __syncthreads();

#pragma unroll
    for (int ks = 0; ks < 4; ks++) {
      const int koff = ks * 8 + 2 * t4;
      uint2 alo[2], ahi[2];
#pragma unroll
      for (int i = 0; i < 2; i++) {
        int row = wm * 32 + i * 16 + g;
        alo[i] = *reinterpret_cast<const uint2*>(&As[row * QST + koff]);
        ahi[i] = *reinterpret_cast<const uint2*>(&As[(row + 8) * QST + koff]);
      }
#pragma unroll
      for (int j = 0; j < 8; j++) {
        int n = wn * 64 + j * 8 + g;
        uint2 b = *reinterpret_cast<const uint2*>(&Bs[n * QST + koff]);
#pragma unroll
        for (int i = 0; i < 2; i++)
          mma8(acc[i][j], alo[i].x, ahi[i].x, alo[i].y, ahi[i].y, b.x, b.y);
      }
    }
  }

  // Epilogue into [nh][t][d], values rounded to tf32 so attn can skip cvt.
  const int h = (e0 >> 6) + wn;
#pragma unroll
  for (int i = 0; i < 2; i++) {
#pragma unroll
    for (int j = 0; j < 8; j++) {
      int d = j * 8 + 2 * t4;
      int m = m0 + wm * 32 + i * 16 + g;
      {
        int n = m >> 11, tt = m & (T_ - 1);
        *reinterpret_cast<float2*>(
            &out[((size_t)(n * H_ + h) * T_ + tt) * D_ + d]) =
            make_float2(__uint_as_float(f2tf(acc[i][j][0])),
                        __uint_as_float(f2tf(acc[i][j][1])));
      }
      {
        int m2 = m + 8;
        int n = m2 >> 11, tt = m2 & (T_ - 1);
        *reinterpret_cast<float2*>(
            &out[((size_t)(n * H_ + h) * T_ + tt) * D_ + d]) =
            make_float2(__uint_as_float(f2tf(acc[i][j][2])),
                        __uint_as_float(f2tf(acc[i][j][3])));
      }
    }
  }
}

// ---------------------------------------------------------------------------
// Flash attention, tf32 mma, pipelined.
// Br=128, Bc=64, 256 threads = 8 warps, warp owns 16 query rows.
// Scratch already tf32 -> plain row layout, stride 68 (conflict-free LDS.32).
// K/V double-buffered via cp.async. P converted C-frag->A-frag by shuffles.
// ---------------------------------------------------------------------------
#define AST 68

__global__ __launch_bounds__(256, 2) void attn_kernel(float* __restrict__ out) {
  extern __shared__ uint32_t sm[];
  uint32_t* Qs  = sm;                    // [128][68]
  uint32_t* Ks0 = Qs + 128 * AST;        // 2 x [64][68]
  uint32_t* Vs0 = Ks0 + 2 * 64 * AST;    // 2 x [64][68]

  const int qb = blockIdx.x;
  const int nh = blockIdx.y;
  const float* __restrict__ Qg = g_q + (size_t)nh * T_ * D_ + (size_t)qb * 128 * D_;
  const float* __restrict__ Kg = g_k + (size_t)nh * T_ * D_;
  const float* __restrict__ Vg = g_v + (size_t)nh * T_ * D_;

  const int tid = threadIdx.x;
  const int lane = tid & 31;
  const int wid = tid >> 5;           // 0..7
  const int g = lane >> 2;
  const int t4 = lane & 3;
  const int wrow = wid * 16 + g;      // A-fragment row (and +8)

  // loader mapping: 16 rows x 16 float4-cols per pass
  const int lr = tid >> 4;            // 0..15
  const int cq = tid & 15;            // 0..15

  const uint32_t qs_base  = (uint32_t)__cvta_generic_to_shared(Qs);
  const uint32_t ks_base  = (uint32_t)__cvta_generic_to_shared(Ks0);
  const uint32_t vs_base  = (uint32_t)__cvta_generic_to_shared(Vs0);

  // Prologue: Q (128 rows) + K/V tile 0, one commit group
#pragma unroll
  for (int p = 0; p < 8; p++) {
    int row = lr + p * 16;
    cp16(qs_base + (row * AST + cq * 4) * 4, &Qg[row * D_ + cq * 4]);
  }
#pragma unroll
  for (int p = 0; p < 4; p++) {
    int row = lr + p * 16;
    cp16(ks_base + (row * AST + cq * 4) * 4, &Kg[row * D_ + cq * 4]);
    cp16(vs_base + (row * AST + cq * 4) * 4, &Vg[row * D_ + cq * 4]);
  }
  cp_commit();

  float o[8][4] = {};
  float mi[2] = {-CUDART_INF_F, -CUDART_INF_F};
  float li[2] = {0.f, 0.f};

  const int src_lo = (lane & 28) | (t4 >> 1);
  const int src_hi = src_lo + 2;
  const bool selhi = (t4 & 1);

  for (int kb = 0; kb < T_ / 64; kb++) {
    const int cur = kb & 1;
    cp_wait0();
    __syncthreads();   // current buffers ready; all warps done with other buffer

    if (kb + 1 < T_ / 64) {
      const int nxt = cur ^ 1;
      const size_t gbase = (size_t)(kb + 1) * 64;
#pragma unroll
      for (int p = 0; p < 4; p++) {
        int row = lr + p * 16;
        cp16(ks_base + ((nxt * 64 + row) * AST + cq * 4) * 4,
             &Kg[(gbase + row) * D_ + cq * 4]);
        cp16(vs_base + ((nxt * 64 + row) * AST + cq * 4) * 4,
             &Vg[(gbase + row) * D_ + cq * 4]);
      }
      cp_commit();
    }

    const uint32_t* Ksc = Ks0 + cur * 64 * AST;
    const uint32_t* Vsc = Vs0 + cur * 64 * AST;

    // ---- S = Q @ K^T : warp computes 16 x 64 ----
    float sacc[8][4] = {};
#pragma unroll
    for (int ks = 0; ks < 8; ks++) {
      const int koff = ks * 8 + t4;
      uint32_t a0 = Qs[wrow * AST + koff];
      uint32_t a1 = Qs[(wrow + 8) * AST + koff];
      uint32_t a2 = Qs[wrow * AST + koff + 4];
      uint32_t a3 = Qs[(wrow + 8) * AST + koff + 4];
#pragma unroll
      for (int j = 0; j < 8; j++) {
        uint32_t b0 = Ksc[(j * 8 + g) * AST + koff];
        uint32_t b1 = Ksc[(j * 8 + g) * AST + koff + 4];
        mma8(sacc[j], a0, a1, a2, a3, b0, b1);
      }
    }

    // ---- online softmax: rows g (slot 0) and g+8 (slot 1) ----
    const float scale = 0.125f;
#pragma unroll
    for (int rh = 0; rh < 2; rh++) {
      float mx = -CUDART_INF_F;
#pragma unroll
      for (int j = 0; j < 8; j++) {
        sacc[j][2 * rh]     *= scale;
        sacc[j][2 * rh + 1] *= scale;
        mx = fmaxf(mx, fmaxf(sacc[j][2 * rh], sacc[j][2 * rh + 1]));
      }
      mx = fmaxf(mx, __shfl_xor_sync(0xffffffffu, mx, 1));
      mx = fmaxf(mx, __shfl_xor_sync(0xffffffffu, mx, 2));
      float mnew = fmaxf(mi[rh], mx);
      float alpha = __expf(mi[rh] - mnew);
      float rs = 0.f;
#pragma unroll
      for (int j = 0; j < 8; j++) {
        sacc[j][2 * rh]     = __expf(sacc[j][2 * rh] - mnew);
        sacc[j][2 * rh + 1] = __expf(sacc[j][2 * rh + 1] - mnew);
        rs += sacc[j][2 * rh] + sacc[j][2 * rh + 1];
      }
      rs += __shfl_xor_sync(0xffffffffu, rs, 1);
      rs += __shfl_xor_sync(0xffffffffu, rs, 2);
      li[rh] = li[rh] * alpha + rs;
      mi[rh] = mnew;
#pragma unroll
      for (int j = 0; j < 8; j++) {
        o[j][2 * rh]     *= alpha;
        o[j][2 * rh + 1] *= alpha;
      }
    }

    // ---- O += P @ V ; P A-fragments built by quad shuffles ----
#pragma unroll
    for (int ks2 = 0; ks2 < 8; ks2++) {
      // C-frag (row g: c0@col 2t4', c1@col 2t4'+1; row g+8: c2,c3)
      //   -> A-frag (a0:(g,t4) a1:(g+8,t4) a2:(g,t4+4) a3:(g+8,t4+4))
      float c0l = __shfl_sync(0xffffffffu, sacc[ks2][0], src_lo);
      float c1l = __shfl_sync(0xffffffffu, sacc[ks2][1], src_lo);
      float c0h = __shfl_sync(0xffffffffu, sacc[ks2][0], src_hi);
      float c1h = __shfl_sync(0xffffffffu, sacc[ks2][1], src_hi);
      float c2l = __shfl_sync(0xffffffffu, sacc[ks2][2], src_lo);
      float c3l = __shfl_sync(0xffffffffu, sacc[ks2][3], src_lo);
      float c2h = __shfl_sync(0xffffffffu, sacc[ks2][2], src_hi);
      float c3h = __shfl_sync(0xffffffffu, sacc[ks2][3], src_hi);
      uint32_t pa0 = f2tf(selhi ? c1l : c0l);
      uint32_t pa1 = f2tf(selhi ? c3l : c2l);
      uint32_t pa2 = f2tf(selhi ? c1h : c0h);
      uint32_t pa3 = f2tf(selhi ? c3h : c2h);
#pragma unroll
      for (int j = 0; j < 8; j++) {
        uint32_t b0 = Vsc[(ks2 * 8 + t4) * AST + j * 8 + g];
        uint32_t b1 = Vsc[(ks2 * 8 + t4 + 4) * AST + j * 8 + g];
        mma8(o[j], pa0, pa1, pa2, pa3, b0, b1);
      }
    }
  }

  // ---- epilogue ----
  const int n = nh / H_;
  const int h = nh - n * H_;
#pragma unroll
  for (int rh = 0; rh < 2; rh++) {
    float inv = 1.f / li[rh];
    int t = qb * 128 + wid * 16 + rh * 8 + g;
#pragma unroll
    for (int j = 0; j < 8; j++) {
      int d = j * 8 + 2 * t4;
      *reinterpret_cast<float2*>(
          &out[((size_t)n * T_ + t) * E_ + h * D_ + d]) =
          make_float2(o[j][2 * rh] * inv, o[j][2 * rh + 1] * inv);
    }
  }
}

extern "C" void kernel_launch(void* const* d_in, const int* in_sizes, int n_in,
                              void* d_out, int out_size) {
  const float* x  = (const float*)d_in[0];
  const float* Wq = (const float*)d_in[1];
  const float* Wk = (const float*)d_in[2];
  const float* Wv = (const float*)d_in[3];
  float* out = (float*)d_out;

  dim3 gq(NT_ / 128, E_ / 128, 3);
  qkv_kernel<<<gq, 256>>>(x, Wq, Wk, Wv);

  const int attn_smem = (128 + 4 * 64) * AST * 4;  // 104448 B
  cudaFuncSetAttribute(attn_kernel, cudaFuncAttributeMaxDynamicSharedMemorySize,
                       attn_smem);
  dim3 ga(T_ / 128, NH_);
  attn_kernel<<<ga, 256, attn_smem>>>(out);
}

// round 6
// speedup vs baseline: 4.5099x; 1.6134x over previous
#include <cuda_runtime.h>
#include <math_constants.h>
#include <cstdint>

// Problem constants
#define N_ 4
#define T_ 2048
#define E_ 768
#define H_ 12
#define D_ 64
#define NT_ (N_*T_)    // 8192
#define NH_ (N_*H_)    // 48
#define EE_ (E_*E_)

// Scratch
__device__ float g_q[NH_*T_*D_];
__device__ float g_k[NH_*T_*D_];
__device__ float g_v[NH_*T_*D_];
__device__ float g_xr[NT_*E_];   // tf32-rounded x
__device__ float g_wr[3*EE_];    // tf32-rounded Wq,Wk,Wv

__device__ __forceinline__ uint32_t f2tf(float f) {
  uint32_t u;
  asm("cvt.rna.tf32.f32 %0, %1;" : "=r"(u) : "f"(f));
  return u;
}

// D = A*B + D, m16n8k8 tf32
__device__ __forceinline__ void mma8(float* c, uint32_t a0, uint32_t a1,
                                     uint32_t a2, uint32_t a3,
                                     uint32_t b0, uint32_t b1) {
  asm volatile(
      "mma.sync.aligned.m16n8k8.row.col.f32.tf32.tf32.f32 "
      "{%0,%1,%2,%3},{%4,%5,%6,%7},{%8,%9},{%0,%1,%2,%3};"
      : "+f"(c[0]), "+f"(c[1]), "+f"(c[2]), "+f"(c[3])
      : "r"(a0), "r"(a1), "r"(a2), "r"(a3), "r"(b0), "r"(b1));
}

__device__ __forceinline__ void cp16(uint32_t smem_addr, const void* gptr) {
  asm volatile("cp.async.cg.shared.global [%0], [%1], 16;"
               :: "r"(smem_addr), "l"(gptr));
}
__device__ __forceinline__ void cp_commit() {
  asm volatile("cp.async.commit_group;");
}
__device__ __forceinline__ void cp_wait0() {
  asm volatile("cp.async.wait_group 0;");
}

// ---------------------------------------------------------------------------
// Pre-round inputs to tf32 (rna) so GEMM mainloops need no conversion.
// dst_sel: 0 -> g_xr, 1..3 -> g_wr + (sel-1)*EE_
// ---------------------------------------------------------------------------
__global__ __launch_bounds__(256) void round_kernel(const float* __restrict__ src,
                                                    int dst_sel, int n4) {
  float* __restrict__ dst = (dst_sel == 0) ? g_xr : (g_wr + (dst_sel - 1) * EE_);
  int i = blockIdx.x * blockDim.x + threadIdx.x;
  if (i < n4) {
    float4 v = reinterpret_cast<const float4*>(src)[i];
    v.x = __uint_as_float(f2tf(v.x));
    v.y = __uint_as_float(f2tf(v.y));
    v.z = __uint_as_float(f2tf(v.z));
    v.w = __uint_as_float(f2tf(v.w));
    reinterpret_cast<float4*>(dst)[i] = v;
  }
}

// ---------------------------------------------------------------------------
// QKV projection (tf32 mma): out[m][e] = sum_k x[m][k]*W[e][k]
// CTA 128(m) x 128(e), BK=32 double-buffered cp.async, 256 threads = 8 warps
// (wm 4 x wn 2), warp tile 32x64. Plain row layout, stride 36 ->
// fragment LDS.32 banks = 4g+t4 (conflict-free).
// ---------------------------------------------------------------------------
#define QST2 36

__global__ __launch_bounds__(256, 2) void qkv_kernel() {
  extern __shared__ uint32_t sm[];
  uint32_t* As = sm;                    // [2][128*36]
  uint32_t* Bs = sm + 2 * 128 * QST2;   // [2][128*36]

  const int which = blockIdx.z;
  const float* __restrict__ X = g_xr;
  const float* __restrict__ W = g_wr + which * EE_;
  float* __restrict__ out = (which == 0) ? g_q : ((which == 1) ? g_k : g_v);

  const int m0 = blockIdx.x * 128;
  const int e0 = blockIdx.y * 128;
  const int tid = threadIdx.x;
  const int lane = tid & 31;
  const int wid = tid >> 5;
  const int wm = wid & 3;
  const int wn = wid >> 2;
  const int g = lane >> 2;
  const int t4 = lane & 3;

  const int lr = tid >> 3;      // 0..31
  const int cq = tid & 7;       // float4 col 0..7

  const uint32_t as_b = (uint32_t)__cvta_generic_to_shared(As);
  const uint32_t bs_b = (uint32_t)__cvta_generic_to_shared(Bs);

  // Prologue: buffer 0
#pragma unroll
  for (int p = 0; p < 4; p++) {
    int row = lr + p * 32;
    cp16(as_b + (row * QST2 + cq * 4) * 4, &X[(m0 + row) * E_ + cq * 4]);
    cp16(bs_b + (row * QST2 + cq * 4) * 4, &W[(e0 + row) * E_ + cq * 4]);
  }
  cp_commit();

  float acc[2][8][4] = {};

  for (int k0 = 0; k0 < E_; k0 += 32) {
    const int cur = (k0 >> 5) & 1;
    cp_wait0();
    __syncthreads();

    if (k0 + 32 < E_) {
      const int nxt = cur ^ 1;
#pragma unroll
      for (int p = 0; p < 4; p++) {
        int row = lr + p * 32;
        cp16(as_b + ((nxt * 128 + row) * QST2 + cq * 4) * 4,
             &X[(m0 + row) * E_ + k0 + 32 + cq * 4]);
        cp16(bs_b + ((nxt * 128 + row) * QST2 + cq * 4) * 4,
             &W[(e0 + row) * E_ + k0 + 32 + cq * 4]);
      }
      cp_commit();
    }

    const uint32_t* Ac = As + cur * 128 * QST2;
    const uint32_t* Bc = Bs + cur * 128 * QST2;

#pragma unroll
    for (int ks = 0; ks < 4; ks++) {
      const int koff = ks * 8 + t4;
      uint32_t a[2][4];
#pragma unroll
      for (int i = 0; i < 2; i++) {
        int row = wm * 32 + i * 16 + g;
        a[i][0] = Ac[row * QST2 + koff];
        a[i][1] = Ac[(row + 8) * QST2 + koff];
        a[i][2] = Ac[row * QST2 + koff + 4];
        a[i][3] = Ac[(row + 8) * QST2 + koff + 4];
      }
#pragma unroll
      for (int j = 0; j < 8; j++) {
        int nrow = wn * 64 + j * 8 + g;
        uint32_t b0 = Bc[nrow * QST2 + koff];
        uint32_t b1 = Bc[nrow * QST2 + koff + 4];
#pragma unroll
        for (int i = 0; i < 2; i++)
          mma8(acc[i][j], a[i][0], a[i][1], a[i][2], a[i][3], b0, b1);
      }
    }
  }

  // Epilogue into [nh][t][d], rounded to tf32 so attn can skip cvt.
  const int h = (e0 >> 6) + wn;
#pragma unroll
  for (int i = 0; i < 2; i++) {
#pragma unroll
    for (int j = 0; j < 8; j++) {
      int d = j * 8 + 2 * t4;
      int m = m0 + wm * 32 + i * 16 + g;
      {
        int n = m >> 11, tt = m & (T_ - 1);
        *reinterpret_cast<float2*>(
            &out[((size_t)(n * H_ + h) * T_ + tt) * D_ + d]) =
            make_float2(__uint_as_float(f2tf(acc[i][j][0])),
                        __uint_as_float(f2tf(acc[i][j][1])));
      }
      {
        int m2 = m + 8;
        int n = m2 >> 11, tt = m2 & (T_ - 1);
        *reinterpret_cast<float2*>(
            &out[((size_t)(n * H_ + h) * T_ + tt) * D_ + d]) =
            make_float2(__uint_as_float(f2tf(acc[i][j][2])),
                        __uint_as_float(f2tf(acc[i][j][3])));
      }
    }
  }
}

// ---------------------------------------------------------------------------
// Flash attention, tf32 mma, pipelined.
// Br=128, Bc=64, 128 threads = 4 warps, warp owns 32 query rows (2 m16 tiles)
// so K/V fragment bytes are amortized over 2x the MMAs.
// Q/K stride 68 (banks 4g+t4, conflict-free); V stride 72 (banks 8t4+g).
// K/V double-buffered via cp.async. P C-frag -> A-frag via quad shuffles.
// ---------------------------------------------------------------------------
#define AST 68
#define VST 72

__global__ __launch_bounds__(128, 2) void attn_kernel(float* __restrict__ out) {
  extern __shared__ uint32_t sm[];
  uint32_t* Qs = sm;                    // [128][68]
  uint32_t* Ks = Qs + 128 * AST;        // [2][64][68]
  uint32_t* Vs = Ks + 2 * 64 * AST;     // [2][64][72]

  const int qb = blockIdx.x;
  const int nh = blockIdx.y;
  const float* __restrict__ Qg = g_q + (size_t)nh * T_ * D_ + (size_t)qb * 128 * D_;
  const float* __restrict__ Kg = g_k + (size_t)nh * T_ * D_;
  const float* __restrict__ Vg = g_v + (size_t)nh * T_ * D_;

  const int tid = threadIdx.x;
  const int lane = tid & 31;
  const int wid = tid >> 5;           // 0..3
  const int g = lane >> 2;
  const int t4 = lane & 3;
  const int wbase = wid * 32;

  const int lr = tid >> 4;            // 0..7
  const int cq = tid & 15;            // 0..15

  const uint32_t qs_b = (uint32_t)__cvta_generic_to_shared(Qs);
  const uint32_t ks_b = (uint32_t)__cvta_generic_to_shared(Ks);
  const uint32_t vs_b = (uint32_t)__cvta_generic_to_shared(Vs);

  // Prologue: Q (128 rows) + K/V tile 0
#pragma unroll
  for (int p = 0; p < 16; p++) {
    int row = lr + p * 8;
    cp16(qs_b + (row * AST + cq * 4) * 4, &Qg[row * D_ + cq * 4]);
  }
#pragma unroll
  for (int p = 0; p < 8; p++) {
    int row = lr + p * 8;
    cp16(ks_b + (row * AST + cq * 4) * 4, &Kg[row * D_ + cq * 4]);
    cp16(vs_b + (row * VST + cq * 4) * 4, &Vg[row * D_ + cq * 4]);
  }
  cp_commit();

  float o[2][8][4] = {};
  float mi[4], li[4];
#pragma unroll
  for (int s = 0; s < 4; s++) { mi[s] = -CUDART_INF_F; li[s] = 0.f; }

  const int src_lo = (lane & 28) | (t4 >> 1);
  const int src_hi = src_lo + 2;
  const bool selhi = (t4 & 1);

  for (int kb = 0; kb < T_ / 64; kb++) {
    const int cur = kb & 1;
    cp_wait0();
    __syncthreads();   // current buffers ready; all warps done with other buffer

    if (kb + 1 < T_ / 64) {
      const int nxt = cur ^ 1;
      const size_t gbase = (size_t)(kb + 1) * 64;
#pragma unroll
      for (int p = 0; p < 8; p++) {
        int row = lr + p * 8;
        cp16(ks_b + ((nxt * 64 + row) * AST + cq * 4) * 4,
             &Kg[(gbase + row) * D_ + cq * 4]);
        cp16(vs_b + ((nxt * 64 + row) * VST + cq * 4) * 4,
             &Vg[(gbase + row) * D_ + cq * 4]);
      }
      cp_commit();
    }

    const uint32_t* Ksc = Ks + cur * 64 * AST;
    const uint32_t* Vsc = Vs + cur * 64 * VST;

    // ---- S = Q @ K^T : warp computes 32 x 64 ----
    float sacc[2][8][4] = {};
#pragma unroll
    for (int ks = 0; ks < 8; ks++) {
      const int koff = ks * 8 + t4;
      uint32_t a[2][4];
#pragma unroll
      for (int i = 0; i < 2; i++) {
        int row = wbase + i * 16 + g;
        a[i][0] = Qs[row * AST + koff];
        a[i][1] = Qs[(row + 8) * AST + koff];
        a[i][2] = Qs[row * AST + koff + 4];
        a[i][3] = Qs[(row + 8) * AST + koff + 4];
      }
#pragma unroll
      for (int j = 0; j < 8; j++) {
        uint32_t b0 = Ksc[(j * 8 + g) * AST + koff];
        uint32_t b1 = Ksc[(j * 8 + g) * AST + koff + 4];
#pragma unroll
        for (int i = 0; i < 2; i++)
          mma8(sacc[i][j], a[i][0], a[i][1], a[i][2], a[i][3], b0, b1);
      }
    }

    // ---- online softmax: 4 row-slots per thread ----
    const float scale = 0.125f;
#pragma unroll
    for (int i = 0; i < 2; i++) {
#pragma unroll
      for (int rh = 0; rh < 2; rh++) {
        const int s = i * 2 + rh;
        float mx = -CUDART_INF_F;
#pragma unroll
        for (int j = 0; j < 8; j++) {
          sacc[i][j][2 * rh]     *= scale;
          sacc[i][j][2 * rh + 1] *= scale;
          mx = fmaxf(mx, fmaxf(sacc[i][j][2 * rh], sacc[i][j][2 * rh + 1]));
        }
        mx = fmaxf(mx, __shfl_xor_sync(0xffffffffu, mx, 1));
        mx = fmaxf(mx, __shfl_xor_sync(0xffffffffu, mx, 2));
        float mnew = fmaxf(mi[s], mx);
        float alpha = __expf(mi[s] - mnew);
        float rs = 0.f;
#pragma unroll
        for (int j = 0; j < 8; j++) {
          sacc[i][j][2 * rh]     = __expf(sacc[i][j][2 * rh] - mnew);
          sacc[i][j][2 * rh + 1] = __expf(sacc[i][j][2 * rh + 1] - mnew);
          rs += sacc[i][j][2 * rh] + sacc[i][j][2 * rh + 1];
        }
        rs += __shfl_xor_sync(0xffffffffu, rs, 1);
        rs += __shfl_xor_sync(0xffffffffu, rs, 2);
        li[s] = li[s] * alpha + rs;
        mi[s] = mnew;
#pragma unroll
        for (int j = 0; j < 8; j++) {
          o[i][j][2 * rh]     *= alpha;
          o[i][j][2 * rh + 1] *= alpha;
        }
      }
    }

    // ---- O += P @ V ; P A-fragments built by quad shuffles ----
#pragma unroll
    for (int ks2 = 0; ks2 < 8; ks2++) {
      uint32_t pa[2][4];
#pragma unroll
      for (int i = 0; i < 2; i++) {
        float c0l = __shfl_sync(0xffffffffu, sacc[i][ks2][0], src_lo);
        float c1l = __shfl_sync(0xffffffffu, sacc[i][ks2][1], src_lo);
        float c0h = __shfl_sync(0xffffffffu, sacc[i][ks2][0], src_hi);
        float c1h = __shfl_sync(0xffffffffu, sacc[i][ks2][1], src_hi);
        float c2l = __shfl_sync(0xffffffffu, sacc[i][ks2][2], src_lo);
        float c3l = __shfl_sync(0xffffffffu, sacc[i][ks2][3], src_lo);
        float c2h = __shfl_sync(0xffffffffu, sacc[i][ks2][2], src_hi);
        float c3h = __shfl_sync(0xffffffffu, sacc[i][ks2][3], src_hi);
        pa[i][0] = f2tf(selhi ? c1l : c0l);
        pa[i][1] = f2tf(selhi ? c3l : c2l);
        pa[i][2] = f2tf(selhi ? c1h : c0h);
        pa[i][3] = f2tf(selhi ? c3h : c2h);
      }
#pragma unroll
      for (int j = 0; j < 8; j++) {
        uint32_t b0 = Vsc[(ks2 * 8 + t4) * VST + j * 8 + g];
        uint32_t b1 = Vsc[(ks2 * 8 + t4 + 4) * VST + j * 8 + g];
        mma8(o[0][j], pa[0][0], pa[0][1], pa[0][2], pa[0][3], b0, b1);
        mma8(o[1][j], pa[1][0], pa[1][1], pa[1][2], pa[1][3], b0, b1);
      }
    }
  }

  // ---- epilogue ----
  const int n = nh / H_;
  const int h = nh - n * H_;
#pragma unroll
  for (int i = 0; i < 2; i++) {
#pragma unroll
    for (int rh = 0; rh < 2; rh++) {
      float inv = 1.f / li[i * 2 + rh];
      int t = qb * 128 + wbase + i * 16 + rh * 8 + g;
#pragma unroll
      for (int j = 0; j < 8; j++) {
        int d = j * 8 + 2 * t4;
        *reinterpret_cast<float2*>(
            &out[((size_t)n * T_ + t) * E_ + h * D_ + d]) =
            make_float2(o[i][j][2 * rh] * inv, o[i][j][2 * rh + 1] * inv);
      }
    }
  }
}

extern "C" void kernel_launch(void* const* d_in, const int* in_sizes, int n_in,
                              void* d_out, int out_size) {
  const float* x  = (const float*)d_in[0];
  const float* Wq = (const float*)d_in[1];
  const float* Wk = (const float*)d_in[2];
  const float* Wv = (const float*)d_in[3];
  float* out = (float*)d_out;

  // Pre-round inputs to tf32
  round_kernel<<<(NT_ * E_ / 4 + 255) / 256, 256>>>(x, 0, NT_ * E_ / 4);
  round_kernel<<<(EE_ / 4 + 255) / 256, 256>>>(Wq, 1, EE_ / 4);
  round_kernel<<<(EE_ / 4 + 255) / 256, 256>>>(Wk, 2, EE_ / 4);
  round_kernel<<<(EE_ / 4 + 255) / 256, 256>>>(Wv, 3, EE_ / 4);

  const int qkv_smem = 4 * 128 * QST2 * 4;  // 73728 B
  cudaFuncSetAttribute(qkv_kernel, cudaFuncAttributeMaxDynamicSharedMemorySize,
                       qkv_smem);
  dim3 gq(NT_ / 128, E_ / 128, 3);
  qkv_kernel<<<gq, 256, qkv_smem>>>();

  const int attn_smem = (128 * AST + 2 * 64 * AST + 2 * 64 * VST) * 4;  // 106496 B
  cudaFuncSetAttribute(attn_kernel, cudaFuncAttributeMaxDynamicSharedMemorySize,
                       attn_smem);
  dim3 ga(T_ / 128, NH_);
  attn_kernel<<<ga, 128, attn_smem>>>(out);
}